// round 15
// baseline (speedup 1.0000x reference)
#include <cuda_runtime.h>
#include <math.h>
#include <stdint.h>

#define NB 32
#define NC 64
#define NL 2048
#define S0 341
#define S1 341
#define S2 343
#define SKP 352      // padded K stride
#define TSP 68       // gram transposed-smem row stride (64 + 4)
#define NROWS 2048   // NB * NC

// bank-conflict-avoiding index padding for the FFT smem arrays
#define SIDX(a) ((a) + ((a) >> 5))
#define FFTPAD 1056  // 1024 + 32

// Scratch (device globals; allocation-free per harness rules)
__device__ float g_bands[3][NROWS][SKP];
__device__ float g_Y[3][NROWS][SKP];
__device__ float g_dist[3][NB][NC][NC];

// ---------------------------------------------------------------------------
// f32x2 helpers (Blackwell packed fp32: FFMA2)
// ---------------------------------------------------------------------------
__device__ __forceinline__ unsigned long long pk2(float lo, float hi) {
    unsigned long long r;
    asm("mov.b64 %0, {%1, %2};" : "=l"(r) : "f"(lo), "f"(hi));
    return r;
}
__device__ __forceinline__ void fma2(unsigned long long& d,
                                     unsigned long long a, unsigned long long b) {
    asm("fma.rn.f32x2 %0, %1, %2, %0;" : "+l"(d) : "l"(a), "l"(b));
}
__device__ __forceinline__ void add2(unsigned long long& d, unsigned long long a) {
    asm("add.rn.f32x2 %0, %0, %1;" : "+l"(d) : "l"(a));
}
__device__ __forceinline__ float2 upk2(unsigned long long v) {
    float lo, hi;
    asm("mov.b64 {%0, %1}, %2;" : "=f"(lo), "=f"(hi) : "l"(v));
    return make_float2(lo, hi);
}

// ---------------------------------------------------------------------------
// Kernel 1: rfft magnitude via real-packed 1024-pt radix-4 FFT
// (R14 version: SIDX padding = conflict-free scatter; 1 sincospif/thread)
// ---------------------------------------------------------------------------
__device__ __forceinline__ unsigned drev10(unsigned n) {
    unsigned r = __brev(n) >> 22;
    return ((r & 0x155u) << 1) | ((r >> 1) & 0x155u);
}

__global__ __launch_bounds__(256) void fft_kernel(const float* __restrict__ X) {
    __shared__ float sre[FFTPAD], sim[FFTPAD], wre[1025], wim[1025];
    const int row = blockIdx.x;
    const int t = threadIdx.x;
    const float2* x2 = (const float2*)(X + (size_t)row * NL);

    // twiddle fill: w(j) = e^{-i*pi*j/512}; quadrants by rotation
    {
        float sn, cs;
        sincospif((float)t * (1.0f / 512.0f), &sn, &cs);
        const float a = cs, b = -sn;
        wre[t]       = a;    wim[t]       = b;
        wre[t + 256] = b;    wim[t + 256] = -a;   // * (-i)
        wre[t + 512] = -a;   wim[t + 512] = -b;   // * (-1)
        wre[t + 768] = -b;   wim[t + 768] = a;    // * (+i)
    }
    if (t == 0) { wre[1024] = -1.0f; wim[1024] = 0.0f; }

    #pragma unroll
    for (int m = 0; m < 4; m++) {
        const int i = t + m * 256;
        const float2 v = x2[i];
        const unsigned dr = drev10((unsigned)i);
        sre[SIDX(dr)] = v.x;
        sim[SIDX(dr)] = v.y;
    }
    __syncthreads();

    // stage 1: contiguous quads, twiddle = 1
    {
        const int s1 = 4 * t + ((4 * t) >> 5);
        const float x0r = sre[s1 + 0], x1r = sre[s1 + 1];
        const float x2r = sre[s1 + 2], x3r = sre[s1 + 3];
        const float x0i = sim[s1 + 0], x1i = sim[s1 + 1];
        const float x2i = sim[s1 + 2], x3i = sim[s1 + 3];
        const float s02r = x0r + x2r, s02i = x0i + x2i;
        const float d02r = x0r - x2r, d02i = x0i - x2i;
        const float s13r = x1r + x3r, s13i = x1i + x3i;
        const float d13r = x1r - x3r, d13i = x1i - x3i;
        sre[s1 + 0] = s02r + s13r;  sim[s1 + 0] = s02i + s13i;
        sre[s1 + 1] = d02r + d13i;  sim[s1 + 1] = d02i - d13r;
        sre[s1 + 2] = s02r - s13r;  sim[s1 + 2] = s02i - s13i;
        sre[s1 + 3] = d02r - d13i;  sim[s1 + 3] = d02i + d13r;
    }
    __syncthreads();

    // stages 2..5
    #pragma unroll
    for (int s = 2; s <= 5; s++) {
        const int mm = 1 << (2 * (s - 1));
        const int j = t & (mm - 1);
        const int base = ((t >> (2 * (s - 1))) << (2 * s)) + j;
        const int r1 = j << (10 - 2 * s);

        const int p0 = SIDX(base);
        const int p1 = SIDX(base + mm);
        const int p2 = SIDX(base + 2 * mm);
        const int p3 = SIDX(base + 3 * mm);

        const float x0r = sre[p0], x0i = sim[p0];
        const float x1r = sre[p1], x1i = sim[p1];
        const float x2r = sre[p2], x2i = sim[p2];
        const float x3r = sre[p3], x3i = sim[p3];
        const float w1r = wre[r1],     w1i = wim[r1];
        const float w2r = wre[2 * r1], w2i = wim[2 * r1];
        const float w3r = wre[3 * r1], w3i = wim[3 * r1];

        const float u1r = x1r * w1r - x1i * w1i, u1i = x1r * w1i + x1i * w1r;
        const float u2r = x2r * w2r - x2i * w2i, u2i = x2r * w2i + x2i * w2r;
        const float u3r = x3r * w3r - x3i * w3i, u3i = x3r * w3i + x3i * w3r;

        const float s02r = x0r + u2r, s02i = x0i + u2i;
        const float d02r = x0r - u2r, d02i = x0i - u2i;
        const float s13r = u1r + u3r, s13i = u1i + u3i;
        const float d13r = u1r - u3r, d13i = u1i - u3i;

        sre[p0] = s02r + s13r;  sim[p0] = s02i + s13i;
        sre[p1] = d02r + d13i;  sim[p1] = d02i - d13r;
        sre[p2] = s02r - s13r;  sim[p2] = s02i - s13i;
        sre[p3] = d02r - d13i;  sim[p3] = d02i + d13r;
        __syncthreads();
    }

    // untangle + magnitude -> zero-padded band slabs
    const float CR = 0.999995293809576f;
    const float CI = -0.003067956762966f;
    for (int pos = t; pos < 3 * SKP; pos += 256) {
        int band, off, k, sk;
        if (pos < SKP)            { band = 0; off = pos;           k = off;       sk = S0; }
        else if (pos < 2 * SKP)   { band = 1; off = pos - SKP;     k = S0 + off;  sk = S1; }
        else                      { band = 2; off = pos - 2 * SKP; k = 682 + off; sk = S2; }
        float mag = 0.0f;
        if (off < sk) {
            const int ka = SIDX(k & 1023);
            const int kb = SIDX((1024 - k) & 1023);
            const float z1r = sre[ka], z1i = sim[ka];
            const float z2r = sre[kb], z2i = sim[kb];
            const float zer = z1r + z2r, zei = z1i - z2i;
            const float zor = z1i + z2i, zoi = z2r - z1r;
            const int m = k >> 1;
            float cs = wre[m], msn = wim[m];
            if (k & 1) {
                const float c2 = cs * CR - msn * CI;
                msn = cs * CI + msn * CR;
                cs = c2;
            }
            const float xr = zer + cs * zor - msn * zoi;
            const float xi = zei + cs * zoi + msn * zor;
            mag = 0.5f * sqrtf(xr * xr + xi * xi);
        }
        (&g_bands[0][0][0])[((size_t)band * NROWS + row) * SKP + off] = mag;
    }
}

// ---------------------------------------------------------------------------
// Kernel 2: Y[k][r][d] = sum_s band[k][r][s] * A_k[d][s]   (R8 version)
// 128(r) x 64(d) tiles, 256 threads, 8x4 row-paired f32x2. grid (6, 16, 3)
// ---------------------------------------------------------------------------
__global__ __launch_bounds__(256) void gemm_kernel(const float* __restrict__ A0,
                                                   const float* __restrict__ A1,
                                                   const float* __restrict__ A2) {
    __shared__ float Xs[2][16][128];
    __shared__ float As[2][16][64];

    const int k = blockIdx.z;
    const int sk = (k == 2) ? S2 : S0;
    const float* A = (k == 0) ? A0 : ((k == 1) ? A1 : A2);
    const int d0 = blockIdx.x * 64;
    const int r0 = blockIdx.y * 128;
    const int t = threadIdx.x;
    const int tx = t & 15;
    const int ty = t >> 4;
    const float* band = &g_bands[k][0][0];

    const int xlr = t & 127;
    const int xlh = (t >> 7) * 8;
    const int alr = t & 63;
    const int alh = (t >> 6) * 4;

    const int ad = d0 + alr;
    const bool dok = ad < sk;
    const float* arow = A + (size_t)ad * sk;

    unsigned long long acc[4][4];
    #pragma unroll
    for (int p = 0; p < 4; p++)
        #pragma unroll
        for (int j = 0; j < 4; j++) acc[p][j] = 0ull;

    float4 bx0, bx1, ba0;

#define LDG_TILE(kt)                                                            \
    do {                                                                        \
        const float* xp = &band[(size_t)(r0 + xlr) * SKP + (kt) + xlh];         \
        bx0 = *(const float4*)xp;  bx1 = *(const float4*)(xp + 4);              \
        const int s_ = (kt) + alh;                                              \
        ba0.x = (dok && s_ + 0 < sk) ? arow[s_ + 0] : 0.0f;                     \
        ba0.y = (dok && s_ + 1 < sk) ? arow[s_ + 1] : 0.0f;                     \
        ba0.z = (dok && s_ + 2 < sk) ? arow[s_ + 2] : 0.0f;                     \
        ba0.w = (dok && s_ + 3 < sk) ? arow[s_ + 3] : 0.0f;                     \
    } while (0)

#define STS_TILE(buf)                                                           \
    do {                                                                        \
        Xs[buf][xlh + 0][xlr] = bx0.x;  Xs[buf][xlh + 1][xlr] = bx0.y;          \
        Xs[buf][xlh + 2][xlr] = bx0.z;  Xs[buf][xlh + 3][xlr] = bx0.w;          \
        Xs[buf][xlh + 4][xlr] = bx1.x;  Xs[buf][xlh + 5][xlr] = bx1.y;          \
        Xs[buf][xlh + 6][xlr] = bx1.z;  Xs[buf][xlh + 7][xlr] = bx1.w;          \
        As[buf][alh + 0][alr] = ba0.x;  As[buf][alh + 1][alr] = ba0.y;          \
        As[buf][alh + 2][alr] = ba0.z;  As[buf][alh + 3][alr] = ba0.w;          \
    } while (0)

    LDG_TILE(0);
    STS_TILE(0);
    __syncthreads();

    const int NT = SKP / 16;  // 22
    for (int kt = 0; kt < NT; kt++) {
        const int buf = kt & 1;
        if (kt + 1 < NT) LDG_TILE((kt + 1) * 16);

        #pragma unroll
        for (int kk = 0; kk < 16; kk++) {
            const ulonglong2 a01 = *(const ulonglong2*)&Xs[buf][kk][ty * 8];
            const ulonglong2 a23 = *(const ulonglong2*)&Xs[buf][kk][ty * 8 + 4];
            const float4 b = *(const float4*)&As[buf][kk][tx * 4];
            const unsigned long long bd0 = pk2(b.x, b.x);
            const unsigned long long bd1 = pk2(b.y, b.y);
            const unsigned long long bd2 = pk2(b.z, b.z);
            const unsigned long long bd3 = pk2(b.w, b.w);
            fma2(acc[0][0], a01.x, bd0);  fma2(acc[0][1], a01.x, bd1);
            fma2(acc[0][2], a01.x, bd2);  fma2(acc[0][3], a01.x, bd3);
            fma2(acc[1][0], a01.y, bd0);  fma2(acc[1][1], a01.y, bd1);
            fma2(acc[1][2], a01.y, bd2);  fma2(acc[1][3], a01.y, bd3);
            fma2(acc[2][0], a23.x, bd0);  fma2(acc[2][1], a23.x, bd1);
            fma2(acc[2][2], a23.x, bd2);  fma2(acc[2][3], a23.x, bd3);
            fma2(acc[3][0], a23.y, bd0);  fma2(acc[3][1], a23.y, bd1);
            fma2(acc[3][2], a23.y, bd2);  fma2(acc[3][3], a23.y, bd3);
        }
        if (kt + 1 < NT) STS_TILE(buf ^ 1);
        __syncthreads();
    }

    const int d = d0 + tx * 4;
    if (d < SKP) {
        #pragma unroll
        for (int p = 0; p < 4; p++) {
            const float2 v0 = upk2(acc[p][0]);
            const float2 v1 = upk2(acc[p][1]);
            const float2 v2 = upk2(acc[p][2]);
            const float2 v3 = upk2(acc[p][3]);
            const int r = r0 + ty * 8 + 2 * p;
            float4 lo = make_float4(v0.x, v1.x, v2.x, v3.x);
            float4 hi = make_float4(v0.y, v1.y, v2.y, v3.y);
            *(float4*)&g_Y[k][r][d]     = lo;
            *(float4*)&g_Y[k][r + 1][d] = hi;
        }
    }
#undef LDG_TILE
#undef STS_TILE
}

// ---------------------------------------------------------------------------
// Kernel 3: per (batch b, band k): dist = relu(q_i + q_j - 2 * Yi.Yj)
// R11 gram: 512 threads = 8 K-groups x 64 threads; each thread an 8x8 tile
// (row-paired f32x2) over 44 d-values -> 1 B/MAC smem traffic. Tree reduce.
// grid (32, 3). Dynamic smem: sYT[352*68] f32 + part[4][64][32] ull.
// ---------------------------------------------------------------------------
__global__ __launch_bounds__(512) void gram_dist_kernel() {
    extern __shared__ float smemf[];
    float* sYT = smemf;                                                  // 352*TSP
    unsigned long long* part = (unsigned long long*)(smemf + SKP * TSP); // [4][64][32]
    __shared__ float q[64];

    const int b = blockIdx.x;
    const int k = blockIdx.y;
    const int t = threadIdx.x;

    // load + transpose: g_Y[k][b*64 + r][*] -> sYT[d][r]
    {
        const int r_ = t & 7;
        const int c4_ = t >> 3;      // 0..63
        const float* src = &g_Y[k][b * 64][0];
        #pragma unroll
        for (int rb = 0; rb < 64; rb += 8) {
            const int r = rb + r_;
            #pragma unroll
            for (int cc = 0; cc < 2; cc++) {
                const int c4 = c4_ + 64 * cc;
                if (c4 < SKP / 4) {
                    const float4 v = *(const float4*)&src[(size_t)r * SKP + c4 * 4];
                    const int d = c4 * 4;
                    sYT[(d + 0) * TSP + r] = v.x;
                    sYT[(d + 1) * TSP + r] = v.y;
                    sYT[(d + 2) * TSP + r] = v.z;
                    sYT[(d + 3) * TSP + r] = v.w;
                }
            }
        }
    }
    __syncthreads();

    const int g = t >> 6;          // K-group 0..7
    const int tg = t & 63;
    const int ty = tg >> 3;        // 8x8 thread grid
    const int tx = tg & 7;
    const int ti = ty * 8;
    const int tj = tx * 8;

    // acc[p][c]: lo = G[ti+2p][tj+c], hi = G[ti+2p+1][tj+c]
    unsigned long long acc[4][8];
    #pragma unroll
    for (int p = 0; p < 4; p++)
        #pragma unroll
        for (int c = 0; c < 8; c++) acc[p][c] = 0ull;

    const float* base = &sYT[g * 44 * TSP];
    #pragma unroll 4
    for (int dd = 0; dd < 44; dd++) {
        const float* rowp = base + dd * TSP;
        const ulonglong2 a01 = *(const ulonglong2*)&rowp[ti];
        const ulonglong2 a23 = *(const ulonglong2*)&rowp[ti + 4];
        const float4 b0 = *(const float4*)&rowp[tj];
        const float4 b1 = *(const float4*)&rowp[tj + 4];
        unsigned long long bd[8];
        bd[0] = pk2(b0.x, b0.x);  bd[1] = pk2(b0.y, b0.y);
        bd[2] = pk2(b0.z, b0.z);  bd[3] = pk2(b0.w, b0.w);
        bd[4] = pk2(b1.x, b1.x);  bd[5] = pk2(b1.y, b1.y);
        bd[6] = pk2(b1.z, b1.z);  bd[7] = pk2(b1.w, b1.w);
        const unsigned long long ap[4] = {a01.x, a01.y, a23.x, a23.y};
        #pragma unroll
        for (int p = 0; p < 4; p++)
            #pragma unroll
            for (int c = 0; c < 8; c++)
                fma2(acc[p][c], ap[p], bd[c]);
    }

    // tree reduction across the 8 K-groups: 8 -> 4 -> 2 -> 1
    unsigned long long* my = &part[(size_t)(g & 3) * 64 * 32 + (size_t)tg * 32];
    __syncthreads();
    if (g >= 4) {
        #pragma unroll
        for (int p = 0; p < 4; p++)
            #pragma unroll
            for (int c = 0; c < 8; c++) my[p * 8 + c] = acc[p][c];
    }
    __syncthreads();
    if (g < 4) {
        #pragma unroll
        for (int p = 0; p < 4; p++)
            #pragma unroll
            for (int c = 0; c < 8; c++) add2(acc[p][c], my[p * 8 + c]);
    }
    __syncthreads();
    if (g == 2 || g == 3) {
        unsigned long long* dst = &part[(size_t)(g - 2) * 64 * 32 + (size_t)tg * 32];
        #pragma unroll
        for (int p = 0; p < 4; p++)
            #pragma unroll
            for (int c = 0; c < 8; c++) dst[p * 8 + c] = acc[p][c];
    }
    __syncthreads();
    if (g < 2) {
        #pragma unroll
        for (int p = 0; p < 4; p++)
            #pragma unroll
            for (int c = 0; c < 8; c++) add2(acc[p][c], my[p * 8 + c]);
    }
    __syncthreads();
    if (g == 1) {
        unsigned long long* dst = &part[(size_t)tg * 32];
        #pragma unroll
        for (int p = 0; p < 4; p++)
            #pragma unroll
            for (int c = 0; c < 8; c++) dst[p * 8 + c] = acc[p][c];
    }
    __syncthreads();
    if (g == 0) {
        #pragma unroll
        for (int p = 0; p < 4; p++)
            #pragma unroll
            for (int c = 0; c < 8; c++) add2(acc[p][c], my[p * 8 + c]);
        // q_i = G_ii from diagonal tiles (diagonal masked downstream)
        if (ty == tx) {
            #pragma unroll
            for (int i = 0; i < 8; i++) {
                const float2 v = upk2(acc[i >> 1][i]);
                q[ti + i] = (i & 1) ? v.y : v.x;
            }
        }
    }
    __syncthreads();

    if (g == 0) {
        float qj[8];
        #pragma unroll
        for (int c = 0; c < 8; c++) qj[c] = q[tj + c];
        #pragma unroll
        for (int p = 0; p < 4; p++) {
            const int r = ti + 2 * p;
            const float qlo = q[r], qhi = q[r + 1];
            float lo[8], hi[8];
            #pragma unroll
            for (int c = 0; c < 8; c++) {
                const float2 v = upk2(acc[p][c]);
                lo[c] = fmaxf(qlo + qj[c] - 2.0f * v.x, 0.0f);
                hi[c] = fmaxf(qhi + qj[c] - 2.0f * v.y, 0.0f);
            }
            *(float4*)&g_dist[k][b][r][tj]         = make_float4(lo[0], lo[1], lo[2], lo[3]);
            *(float4*)&g_dist[k][b][r][tj + 4]     = make_float4(lo[4], lo[5], lo[6], lo[7]);
            *(float4*)&g_dist[k][b][r + 1][tj]     = make_float4(hi[0], hi[1], hi[2], hi[3]);
            *(float4*)&g_dist[k][b][r + 1][tj + 4] = make_float4(hi[4], hi[5], hi[6], hi[7]);
        }
    }
}

// ---------------------------------------------------------------------------
// Kernel 4: mask (R13 version — single logf)
// ---------------------------------------------------------------------------
__global__ __launch_bounds__(256) void mask_kernel(const float* __restrict__ fw,
                                                   const float* __restrict__ gum,
                                                   float* __restrict__ out) {
    const int t = threadIdx.x;
    const int g = t >> 6;
    const int j = t & 63;
    const int bi = blockIdx.x * 4 + g;
    const int b = bi >> 6;
    const int i = bi & 63;

    const float f0 = fw[0], f1 = fw[1], f2 = fw[2];
    const float m = fmaxf(f0, fmaxf(f1, f2));
    const float e0 = expf(f0 - m), e1 = expf(f1 - m), e2 = expf(f2 - m);
    const float inv = 1.0f / (e0 + e1 + e2);
    const float w0 = e0 * inv, w1 = e1 * inv, w2 = e2 * inv;

    const float dsum = g_dist[0][b][i][j] * w0
                     + g_dist[1][b][i][j] * w1
                     + g_dist[2][b][i][j] * w2;

    const float e = 1.0f / (dsum + 1e-10f);
    const float emask = (j == i) ? 0.0f : e;

    __shared__ float red[8];
    float v = emask;
    #pragma unroll
    for (int o = 16; o; o >>= 1) v = fmaxf(v, __shfl_xor_sync(0xffffffffu, v, o));
    if ((t & 31) == 0) red[t >> 5] = v;
    __syncthreads();
    const float emax = fmaxf(red[2 * g], red[2 * g + 1]);

    float p = emask / emax;
    p = (j == i) ? 0.99f : p * 0.99f;

    const float l0 = logf(p / (1.0f - p));   // l1 = -l0 exactly in R

    const size_t gidx = ((size_t)(b * 4096 + i * 64 + j)) * 2;
    const float y0 = l0 + gum[gidx + 0];
    const float y1 = -l0 + gum[gidx + 1];

    out[b * 4096 + i * 64 + j] = (y0 >= y1) ? 1.0f : 0.0f;
}

// ---------------------------------------------------------------------------
extern "C" void kernel_launch(void* const* d_in, const int* in_sizes, int n_in,
                              void* d_out, int out_size) {
    const float* X   = (const float*)d_in[0];
    const float* A0  = (const float*)d_in[1];
    const float* A1  = (const float*)d_in[2];
    const float* A2  = (const float*)d_in[3];
    const float* fw  = (const float*)d_in[4];
    const float* gum = (const float*)d_in[5];
    float* out = (float*)d_out;

    fft_kernel<<<NROWS, 256>>>(X);
    gemm_kernel<<<dim3(6, 16, 3), 256>>>(A0, A1, A2);

    const int smem3 = SKP * TSP * sizeof(float)
                    + 4 * 64 * 32 * sizeof(unsigned long long);   // 95.7KB + 64KB
    cudaFuncSetAttribute(gram_dist_kernel,
                         cudaFuncAttributeMaxDynamicSharedMemorySize, smem3);
    gram_dist_kernel<<<dim3(NB, 3), 512, smem3>>>();

    mask_kernel<<<512, 256>>>(fw, gum, out);
}

// round 17
// speedup vs baseline: 1.6184x; 1.6184x over previous
#include <cuda_runtime.h>
#include <math.h>
#include <stdint.h>

#define NB 32
#define NC 64
#define NL 2048
#define S0 341
#define S1 341
#define S2 343
#define SKP 352      // padded K stride
#define TSP 68       // gram transposed-smem row stride (64 + 4)
#define NROWS 2048   // NB * NC
#define PSTR 9       // gram partial-buffer per-thread stride in ull (conflict pad)

// bank-conflict-avoiding index padding for the FFT smem arrays
#define SIDX(a) ((a) + ((a) >> 5))
#define FFTPAD 1056  // 1024 + 32

// Scratch (device globals; allocation-free per harness rules)
__device__ float g_bands[3][NROWS][SKP];
__device__ float g_Y[3][NROWS][SKP];
__device__ float g_dist[3][NB][NC][NC];

// ---------------------------------------------------------------------------
// f32x2 helpers (Blackwell packed fp32: FFMA2)
// ---------------------------------------------------------------------------
__device__ __forceinline__ unsigned long long pk2(float lo, float hi) {
    unsigned long long r;
    asm("mov.b64 %0, {%1, %2};" : "=l"(r) : "f"(lo), "f"(hi));
    return r;
}
__device__ __forceinline__ void fma2(unsigned long long& d,
                                     unsigned long long a, unsigned long long b) {
    asm("fma.rn.f32x2 %0, %1, %2, %0;" : "+l"(d) : "l"(a), "l"(b));
}
__device__ __forceinline__ void add2(unsigned long long& d, unsigned long long a) {
    asm("add.rn.f32x2 %0, %0, %1;" : "+l"(d) : "l"(a));
}
__device__ __forceinline__ float2 upk2(unsigned long long v) {
    float lo, hi;
    asm("mov.b64 {%0, %1}, %2;" : "=f"(lo), "=f"(hi) : "l"(v));
    return make_float2(lo, hi);
}

// ---------------------------------------------------------------------------
// Kernel 1: rfft magnitude via real-packed 1024-pt radix-4 FFT
// (R14 version: SIDX padding = conflict-free scatter; 1 sincospif/thread)
// ---------------------------------------------------------------------------
__device__ __forceinline__ unsigned drev10(unsigned n) {
    unsigned r = __brev(n) >> 22;
    return ((r & 0x155u) << 1) | ((r >> 1) & 0x155u);
}

__global__ __launch_bounds__(256) void fft_kernel(const float* __restrict__ X) {
    __shared__ float sre[FFTPAD], sim[FFTPAD], wre[1025], wim[1025];
    const int row = blockIdx.x;
    const int t = threadIdx.x;
    const float2* x2 = (const float2*)(X + (size_t)row * NL);

    // twiddle fill: w(j) = e^{-i*pi*j/512}; quadrants by rotation
    {
        float sn, cs;
        sincospif((float)t * (1.0f / 512.0f), &sn, &cs);
        const float a = cs, b = -sn;
        wre[t]       = a;    wim[t]       = b;
        wre[t + 256] = b;    wim[t + 256] = -a;   // * (-i)
        wre[t + 512] = -a;   wim[t + 512] = -b;   // * (-1)
        wre[t + 768] = -b;   wim[t + 768] = a;    // * (+i)
    }
    if (t == 0) { wre[1024] = -1.0f; wim[1024] = 0.0f; }

    #pragma unroll
    for (int m = 0; m < 4; m++) {
        const int i = t + m * 256;
        const float2 v = x2[i];
        const unsigned dr = drev10((unsigned)i);
        sre[SIDX(dr)] = v.x;
        sim[SIDX(dr)] = v.y;
    }
    __syncthreads();

    // stage 1: contiguous quads, twiddle = 1
    {
        const int s1 = 4 * t + ((4 * t) >> 5);
        const float x0r = sre[s1 + 0], x1r = sre[s1 + 1];
        const float x2r = sre[s1 + 2], x3r = sre[s1 + 3];
        const float x0i = sim[s1 + 0], x1i = sim[s1 + 1];
        const float x2i = sim[s1 + 2], x3i = sim[s1 + 3];
        const float s02r = x0r + x2r, s02i = x0i + x2i;
        const float d02r = x0r - x2r, d02i = x0i - x2i;
        const float s13r = x1r + x3r, s13i = x1i + x3i;
        const float d13r = x1r - x3r, d13i = x1i - x3i;
        sre[s1 + 0] = s02r + s13r;  sim[s1 + 0] = s02i + s13i;
        sre[s1 + 1] = d02r + d13i;  sim[s1 + 1] = d02i - d13r;
        sre[s1 + 2] = s02r - s13r;  sim[s1 + 2] = s02i - s13i;
        sre[s1 + 3] = d02r - d13i;  sim[s1 + 3] = d02i + d13r;
    }
    __syncthreads();

    // stages 2..5
    #pragma unroll
    for (int s = 2; s <= 5; s++) {
        const int mm = 1 << (2 * (s - 1));
        const int j = t & (mm - 1);
        const int base = ((t >> (2 * (s - 1))) << (2 * s)) + j;
        const int r1 = j << (10 - 2 * s);

        const int p0 = SIDX(base);
        const int p1 = SIDX(base + mm);
        const int p2 = SIDX(base + 2 * mm);
        const int p3 = SIDX(base + 3 * mm);

        const float x0r = sre[p0], x0i = sim[p0];
        const float x1r = sre[p1], x1i = sim[p1];
        const float x2r = sre[p2], x2i = sim[p2];
        const float x3r = sre[p3], x3i = sim[p3];
        const float w1r = wre[r1],     w1i = wim[r1];
        const float w2r = wre[2 * r1], w2i = wim[2 * r1];
        const float w3r = wre[3 * r1], w3i = wim[3 * r1];

        const float u1r = x1r * w1r - x1i * w1i, u1i = x1r * w1i + x1i * w1r;
        const float u2r = x2r * w2r - x2i * w2i, u2i = x2r * w2i + x2i * w2r;
        const float u3r = x3r * w3r - x3i * w3i, u3i = x3r * w3i + x3i * w3r;

        const float s02r = x0r + u2r, s02i = x0i + u2i;
        const float d02r = x0r - u2r, d02i = x0i - u2i;
        const float s13r = u1r + u3r, s13i = u1i + u3i;
        const float d13r = u1r - u3r, d13i = u1i - u3i;

        sre[p0] = s02r + s13r;  sim[p0] = s02i + s13i;
        sre[p1] = d02r + d13i;  sim[p1] = d02i - d13r;
        sre[p2] = s02r - s13r;  sim[p2] = s02i - s13i;
        sre[p3] = d02r - d13i;  sim[p3] = d02i + d13r;
        __syncthreads();
    }

    // untangle + magnitude -> zero-padded band slabs
    const float CR = 0.999995293809576f;
    const float CI = -0.003067956762966f;
    for (int pos = t; pos < 3 * SKP; pos += 256) {
        int band, off, k, sk;
        if (pos < SKP)            { band = 0; off = pos;           k = off;       sk = S0; }
        else if (pos < 2 * SKP)   { band = 1; off = pos - SKP;     k = S0 + off;  sk = S1; }
        else                      { band = 2; off = pos - 2 * SKP; k = 682 + off; sk = S2; }
        float mag = 0.0f;
        if (off < sk) {
            const int ka = SIDX(k & 1023);
            const int kb = SIDX((1024 - k) & 1023);
            const float z1r = sre[ka], z1i = sim[ka];
            const float z2r = sre[kb], z2i = sim[kb];
            const float zer = z1r + z2r, zei = z1i - z2i;
            const float zor = z1i + z2i, zoi = z2r - z1r;
            const int m = k >> 1;
            float cs = wre[m], msn = wim[m];
            if (k & 1) {
                const float c2 = cs * CR - msn * CI;
                msn = cs * CI + msn * CR;
                cs = c2;
            }
            const float xr = zer + cs * zor - msn * zoi;
            const float xi = zei + cs * zoi + msn * zor;
            mag = 0.5f * sqrtf(xr * xr + xi * xi);
        }
        (&g_bands[0][0][0])[((size_t)band * NROWS + row) * SKP + off] = mag;
    }
}

// ---------------------------------------------------------------------------
// Kernel 2: Y[k][r][d] = sum_s band[k][r][s] * A_k[d][s]   (R8 version)
// 128(r) x 64(d) tiles, 256 threads, 8x4 row-paired f32x2. grid (6, 16, 3)
// ---------------------------------------------------------------------------
__global__ __launch_bounds__(256) void gemm_kernel(const float* __restrict__ A0,
                                                   const float* __restrict__ A1,
                                                   const float* __restrict__ A2) {
    __shared__ float Xs[2][16][128];
    __shared__ float As[2][16][64];

    const int k = blockIdx.z;
    const int sk = (k == 2) ? S2 : S0;
    const float* A = (k == 0) ? A0 : ((k == 1) ? A1 : A2);
    const int d0 = blockIdx.x * 64;
    const int r0 = blockIdx.y * 128;
    const int t = threadIdx.x;
    const int tx = t & 15;
    const int ty = t >> 4;
    const float* band = &g_bands[k][0][0];

    const int xlr = t & 127;
    const int xlh = (t >> 7) * 8;
    const int alr = t & 63;
    const int alh = (t >> 6) * 4;

    const int ad = d0 + alr;
    const bool dok = ad < sk;
    const float* arow = A + (size_t)ad * sk;

    unsigned long long acc[4][4];
    #pragma unroll
    for (int p = 0; p < 4; p++)
        #pragma unroll
        for (int j = 0; j < 4; j++) acc[p][j] = 0ull;

    float4 bx0, bx1, ba0;

#define LDG_TILE(kt)                                                            \
    do {                                                                        \
        const float* xp = &band[(size_t)(r0 + xlr) * SKP + (kt) + xlh];         \
        bx0 = *(const float4*)xp;  bx1 = *(const float4*)(xp + 4);              \
        const int s_ = (kt) + alh;                                              \
        ba0.x = (dok && s_ + 0 < sk) ? arow[s_ + 0] : 0.0f;                     \
        ba0.y = (dok && s_ + 1 < sk) ? arow[s_ + 1] : 0.0f;                     \
        ba0.z = (dok && s_ + 2 < sk) ? arow[s_ + 2] : 0.0f;                     \
        ba0.w = (dok && s_ + 3 < sk) ? arow[s_ + 3] : 0.0f;                     \
    } while (0)

#define STS_TILE(buf)                                                           \
    do {                                                                        \
        Xs[buf][xlh + 0][xlr] = bx0.x;  Xs[buf][xlh + 1][xlr] = bx0.y;          \
        Xs[buf][xlh + 2][xlr] = bx0.z;  Xs[buf][xlh + 3][xlr] = bx0.w;          \
        Xs[buf][xlh + 4][xlr] = bx1.x;  Xs[buf][xlh + 5][xlr] = bx1.y;          \
        Xs[buf][xlh + 6][xlr] = bx1.z;  Xs[buf][xlh + 7][xlr] = bx1.w;          \
        As[buf][alh + 0][alr] = ba0.x;  As[buf][alh + 1][alr] = ba0.y;          \
        As[buf][alh + 2][alr] = ba0.z;  As[buf][alh + 3][alr] = ba0.w;          \
    } while (0)

    LDG_TILE(0);
    STS_TILE(0);
    __syncthreads();

    const int NT = SKP / 16;  // 22
    for (int kt = 0; kt < NT; kt++) {
        const int buf = kt & 1;
        if (kt + 1 < NT) LDG_TILE((kt + 1) * 16);

        #pragma unroll
        for (int kk = 0; kk < 16; kk++) {
            const ulonglong2 a01 = *(const ulonglong2*)&Xs[buf][kk][ty * 8];
            const ulonglong2 a23 = *(const ulonglong2*)&Xs[buf][kk][ty * 8 + 4];
            const float4 b = *(const float4*)&As[buf][kk][tx * 4];
            const unsigned long long bd0 = pk2(b.x, b.x);
            const unsigned long long bd1 = pk2(b.y, b.y);
            const unsigned long long bd2 = pk2(b.z, b.z);
            const unsigned long long bd3 = pk2(b.w, b.w);
            fma2(acc[0][0], a01.x, bd0);  fma2(acc[0][1], a01.x, bd1);
            fma2(acc[0][2], a01.x, bd2);  fma2(acc[0][3], a01.x, bd3);
            fma2(acc[1][0], a01.y, bd0);  fma2(acc[1][1], a01.y, bd1);
            fma2(acc[1][2], a01.y, bd2);  fma2(acc[1][3], a01.y, bd3);
            fma2(acc[2][0], a23.x, bd0);  fma2(acc[2][1], a23.x, bd1);
            fma2(acc[2][2], a23.x, bd2);  fma2(acc[2][3], a23.x, bd3);
            fma2(acc[3][0], a23.y, bd0);  fma2(acc[3][1], a23.y, bd1);
            fma2(acc[3][2], a23.y, bd2);  fma2(acc[3][3], a23.y, bd3);
        }
        if (kt + 1 < NT) STS_TILE(buf ^ 1);
        __syncthreads();
    }

    const int d = d0 + tx * 4;
    if (d < SKP) {
        #pragma unroll
        for (int p = 0; p < 4; p++) {
            const float2 v0 = upk2(acc[p][0]);
            const float2 v1 = upk2(acc[p][1]);
            const float2 v2 = upk2(acc[p][2]);
            const float2 v3 = upk2(acc[p][3]);
            const int r = r0 + ty * 8 + 2 * p;
            float4 lo = make_float4(v0.x, v1.x, v2.x, v3.x);
            float4 hi = make_float4(v0.y, v1.y, v2.y, v3.y);
            *(float4*)&g_Y[k][r][d]     = lo;
            *(float4*)&g_Y[k][r + 1][d] = hi;
        }
    }
#undef LDG_TILE
#undef STS_TILE
}

// ---------------------------------------------------------------------------
// Kernel 3: gram/dist (R8 structure — 1024 threads, 4-way K-split)
// with PSTR=9 padded partial buffers: combine-phase conflicts 16-way -> 2-way
// ---------------------------------------------------------------------------
__global__ __launch_bounds__(1024) void gram_dist_kernel() {
    extern __shared__ float smemf[];
    float* sYT = smemf;                                                  // 352*TSP
    unsigned long long* part = (unsigned long long*)(smemf + SKP * TSP); // [3][256][PSTR]
    __shared__ float q[64];

    const int b = blockIdx.x;
    const int k = blockIdx.y;
    const int t = threadIdx.x;

    {
        const int r_ = t & 7;
        const int c4 = t >> 3;       // 0..127
        if (c4 < SKP / 4) {
            const float* src = &g_Y[k][b * 64][0];
            #pragma unroll
            for (int rb = 0; rb < 64; rb += 8) {
                const int r = rb + r_;
                const float4 v = *(const float4*)&src[(size_t)r * SKP + c4 * 4];
                const int d = c4 * 4;
                sYT[(d + 0) * TSP + r] = v.x;
                sYT[(d + 1) * TSP + r] = v.y;
                sYT[(d + 2) * TSP + r] = v.z;
                sYT[(d + 3) * TSP + r] = v.w;
            }
        }
    }
    __syncthreads();

    const int half = t >> 8;       // K-split group 0..3
    const int tt = t & 255;
    const int ty = tt >> 4;
    const int tx = tt & 15;
    const int ti = ty * 4;
    const int tj = tx * 4;

    unsigned long long acc[2][4];
    #pragma unroll
    for (int p = 0; p < 2; p++)
        #pragma unroll
        for (int j = 0; j < 4; j++) acc[p][j] = 0ull;

    const float* base = &sYT[half * 88 * TSP];
    #pragma unroll 4
    for (int dd = 0; dd < 88; dd++) {
        const float* rowp = base + dd * TSP;
        const ulonglong2 a = *(const ulonglong2*)&rowp[ti];
        const float4 bb = *(const float4*)&rowp[tj];
        const unsigned long long bd0 = pk2(bb.x, bb.x);
        const unsigned long long bd1 = pk2(bb.y, bb.y);
        const unsigned long long bd2 = pk2(bb.z, bb.z);
        const unsigned long long bd3 = pk2(bb.w, bb.w);
        fma2(acc[0][0], a.x, bd0);  fma2(acc[0][1], a.x, bd1);
        fma2(acc[0][2], a.x, bd2);  fma2(acc[0][3], a.x, bd3);
        fma2(acc[1][0], a.y, bd0);  fma2(acc[1][1], a.y, bd1);
        fma2(acc[1][2], a.y, bd2);  fma2(acc[1][3], a.y, bd3);
    }

    if (half != 0) {
        unsigned long long* dst = &part[(size_t)((half - 1) * 256 + tt) * PSTR];
        #pragma unroll
        for (int p = 0; p < 2; p++)
            #pragma unroll
            for (int j = 0; j < 4; j++) dst[p * 4 + j] = acc[p][j];
    }
    __syncthreads();

    if (half == 0) {
        #pragma unroll
        for (int h = 0; h < 3; h++) {
            const unsigned long long* src = &part[(size_t)(h * 256 + tt) * PSTR];
            #pragma unroll
            for (int p = 0; p < 2; p++)
                #pragma unroll
                for (int j = 0; j < 4; j++) add2(acc[p][j], src[p * 4 + j]);
        }
        if (ty == tx) {
            q[ti + 0] = upk2(acc[0][0]).x;
            q[ti + 1] = upk2(acc[0][1]).y;
            q[ti + 2] = upk2(acc[1][2]).x;
            q[ti + 3] = upk2(acc[1][3]).y;
        }
    }
    __syncthreads();

    if (half == 0) {
        #pragma unroll
        for (int p = 0; p < 2; p++) {
            const float2 g0 = upk2(acc[p][0]);
            const float2 g1 = upk2(acc[p][1]);
            const float2 g2 = upk2(acc[p][2]);
            const float2 g3 = upk2(acc[p][3]);
            const float qj0 = q[tj + 0], qj1 = q[tj + 1];
            const float qj2 = q[tj + 2], qj3 = q[tj + 3];
            const int r = ti + 2 * p;
            const float qlo = q[r], qhi = q[r + 1];
            float4 lo, hi;
            lo.x = fmaxf(qlo + qj0 - 2.0f * g0.x, 0.0f);
            lo.y = fmaxf(qlo + qj1 - 2.0f * g1.x, 0.0f);
            lo.z = fmaxf(qlo + qj2 - 2.0f * g2.x, 0.0f);
            lo.w = fmaxf(qlo + qj3 - 2.0f * g3.x, 0.0f);
            hi.x = fmaxf(qhi + qj0 - 2.0f * g0.y, 0.0f);
            hi.y = fmaxf(qhi + qj1 - 2.0f * g1.y, 0.0f);
            hi.z = fmaxf(qhi + qj2 - 2.0f * g2.y, 0.0f);
            hi.w = fmaxf(qhi + qj3 - 2.0f * g3.y, 0.0f);
            *(float4*)&g_dist[k][b][r][tj]     = lo;
            *(float4*)&g_dist[k][b][r + 1][tj] = hi;
        }
    }
}

// ---------------------------------------------------------------------------
// Kernel 4: mask (R13 version — single logf)
// ---------------------------------------------------------------------------
__global__ __launch_bounds__(256) void mask_kernel(const float* __restrict__ fw,
                                                   const float* __restrict__ gum,
                                                   float* __restrict__ out) {
    const int t = threadIdx.x;
    const int g = t >> 6;
    const int j = t & 63;
    const int bi = blockIdx.x * 4 + g;
    const int b = bi >> 6;
    const int i = bi & 63;

    const float f0 = fw[0], f1 = fw[1], f2 = fw[2];
    const float m = fmaxf(f0, fmaxf(f1, f2));
    const float e0 = expf(f0 - m), e1 = expf(f1 - m), e2 = expf(f2 - m);
    const float inv = 1.0f / (e0 + e1 + e2);
    const float w0 = e0 * inv, w1 = e1 * inv, w2 = e2 * inv;

    const float dsum = g_dist[0][b][i][j] * w0
                     + g_dist[1][b][i][j] * w1
                     + g_dist[2][b][i][j] * w2;

    const float e = 1.0f / (dsum + 1e-10f);
    const float emask = (j == i) ? 0.0f : e;

    __shared__ float red[8];
    float v = emask;
    #pragma unroll
    for (int o = 16; o; o >>= 1) v = fmaxf(v, __shfl_xor_sync(0xffffffffu, v, o));
    if ((t & 31) == 0) red[t >> 5] = v;
    __syncthreads();
    const float emax = fmaxf(red[2 * g], red[2 * g + 1]);

    float p = emask / emax;
    p = (j == i) ? 0.99f : p * 0.99f;

    const float l0 = logf(p / (1.0f - p));   // l1 = -l0 exactly in R

    const size_t gidx = ((size_t)(b * 4096 + i * 64 + j)) * 2;
    const float y0 = l0 + gum[gidx + 0];
    const float y1 = -l0 + gum[gidx + 1];

    out[b * 4096 + i * 64 + j] = (y0 >= y1) ? 1.0f : 0.0f;
}

// ---------------------------------------------------------------------------
extern "C" void kernel_launch(void* const* d_in, const int* in_sizes, int n_in,
                              void* d_out, int out_size) {
    const float* X   = (const float*)d_in[0];
    const float* A0  = (const float*)d_in[1];
    const float* A1  = (const float*)d_in[2];
    const float* A2  = (const float*)d_in[3];
    const float* fw  = (const float*)d_in[4];
    const float* gum = (const float*)d_in[5];
    float* out = (float*)d_out;

    fft_kernel<<<NROWS, 256>>>(X);
    gemm_kernel<<<dim3(6, 16, 3), 256>>>(A0, A1, A2);

    const int smem3 = SKP * TSP * sizeof(float)
                    + 3 * 256 * PSTR * sizeof(unsigned long long);
    cudaFuncSetAttribute(gram_dist_kernel,
                         cudaFuncAttributeMaxDynamicSharedMemorySize, smem3);
    gram_dist_kernel<<<dim3(NB, 3), 1024, smem3>>>();

    mask_kernel<<<512, 256>>>(fw, gum, out);
}